// round 12
// baseline (speedup 1.0000x reference)
#include <cuda_runtime.h>

#define BB 1024
#define PP 128
#define MM 127

typedef unsigned long long ull;

#define NPAIR 8256          // 128*129/2
#define KSPLIT 32
#define KPER 272            // per-split pair count (17 chunks of 16); 32*272 = 8704
#define NPAD (KSPLIT * KPER)

// ---------------------------------------------------------------------------
// Static device scratch (allocation-free)
// ---------------------------------------------------------------------------
__device__ float g_Upad[127 * 127 * 128];     // [t][s][k-pad]   8.3 MB
__device__ float g_W1s[NPAD * 128];           // [pair][k-pad]   4.5 MB (sym-folded)
__device__ int   g_pmap[NPAD];                // pair -> i*128+j (pad -> 0)
__device__ float g_z0p[32 * 1024 * 128];      // split-K partials
__device__ float g_z0[1024 * 128];            // [b][k-pad]
__device__ float g_dz[1024 * 127 * 128];      // [b][t][k-pad]  66.6 MB

// ---------------------------------------------------------------------------
// f32x2 packed-FMA helpers
// ---------------------------------------------------------------------------
__device__ __forceinline__ ull dup2(float x) {
    ull u; asm("mov.b64 %0, {%1, %1};" : "=l"(u) : "r"(__float_as_uint(x))); return u;
}
__device__ __forceinline__ void unpack2(ull u, float& lo, float& hi) {
    unsigned int a, b;
    asm("mov.b64 {%0, %1}, %2;" : "=r"(a), "=r"(b) : "l"(u));
    lo = __uint_as_float(a); hi = __uint_as_float(b);
}
__device__ __forceinline__ void fma2(ull& d, ull a, ull b) {
    asm("fma.rn.f32x2 %0, %1, %2, %0;" : "+l"(d) : "l"(a), "l"(b));
}

// 512-thread mapping: tx = tid&31 (4 cols), ty = tid>>5 (8 rows).
// acc2[i2][j]: rows ty*8+2*i2{,+1}, col tx*4+j. A-side LDS is warp-broadcast.
__device__ __forceinline__ void mma_step512(ull acc2[4][4],
                                            const float* __restrict__ Arow,
                                            const float* __restrict__ Bcol) {
    ulonglong2 aA = *(const ulonglong2*)(Arow);
    ulonglong2 aB = *(const ulonglong2*)(Arow + 4);
    float4 b = *(const float4*)(Bcol);
    ull a2[4] = {aA.x, aA.y, aB.x, aB.y};
    ull bd[4] = {dup2(b.x), dup2(b.y), dup2(b.z), dup2(b.w)};
#pragma unroll
    for (int i2 = 0; i2 < 4; i2++)
#pragma unroll
        for (int j = 0; j < 4; j++) fma2(acc2[i2][j], a2[i2], bd[j]);
}

// ---------------------------------------------------------------------------
// Merged builder: blocks [0,508) build U; [508,636) build W1s; [636,640) pmap.
// ---------------------------------------------------------------------------
__global__ void k_build(const float* __restrict__ W1) {
    int bx = blockIdx.x;
    int k = threadIdx.x;

    if (bx < 508) {                        // ---- U[t][s][k] ----
        int t = bx % 127;
        int s0 = (bx / 127) * 32;
        int s1 = s0 + 32 < 127 ? s0 + 32 : 127;
        float winf = (k < MM) ? W1[16256 * 127 + k] : 0.f;
        for (int s = s0; s < s1; s++) {
            float u = 0.f;
            if (k < MM) {
                if (s == t)
                    u = W1[(t * 127 + t) * 127 + k] - winf;
                else
                    u = W1[(t * 127 + s) * 127 + k]
                      + W1[(s * 127 + t) * 127 + k]
                      - W1[(16129 + s) * 127 + k];
            }
            g_Upad[(t * 127 + s) * 128 + k] = u;
        }
    } else if (bx < 636) {                 // ---- W1s[pair][k] (sym-folded) ----
        int i = bx - 508;
        int base = i * 128 - (i * (i - 1)) / 2;
        for (int j = i; j < 128; j++) {
            int p = base + (j - i);
            float v = 0.f;
            if (k < 127) {
                if (i == 0 && j == 0)      v = W1[16256 * 127 + k];
                else if (i == 0)           v = W1[(16129 + j - 1) * 127 + k];
                else if (i == j)           v = W1[((i - 1) * 127 + (i - 1)) * 127 + k];
                else                       v = W1[((i - 1) * 127 + (j - 1)) * 127 + k]
                                             + W1[((j - 1) * 127 + (i - 1)) * 127 + k];
            }
            g_W1s[p * 128 + k] = v;
        }
        for (int p = NPAIR + i; p < NPAD; p += 128)
            g_W1s[p * 128 + k] = 0.f;
    } else {                               // ---- pmap ----
        int i = (bx - 636) * 32 + (k >> 2);
        int lane = k & 3;
        if (i < 128) {
            int base = i * 128 - (i * (i - 1)) / 2;
            for (int j = i + lane; j < 128; j += 4)
                g_pmap[base + (j - i)] = i * 128 + j;
        }
        if (bx == 636) {
            for (int p = NPAIR + k; p < NPAD; p += 128) g_pmap[p] = 0;
        }
    }
}

// ---------------------------------------------------------------------------
// z0 GEMM (symmetric-packed): [1024, 8704] @ [8704, 128], split-K=32.
// ---------------------------------------------------------------------------
__global__ void __launch_bounds__(512, 2) k_z0s(const float* __restrict__ Theta) {
    extern __shared__ float sm[];
    float* As = sm;
    float* Bs = sm + 2 * 16 * 132;
    int* spmap = (int*)(sm + 2 * 16 * 132 + 2 * 16 * 128);
    const int tid = threadIdx.x, tx = tid & 31, ty = tid >> 5;
    const int b0 = blockIdx.x * 128;
    const int kbase = blockIdx.y * KPER;

    for (int q = tid; q < KPER; q += 512) spmap[q] = g_pmap[kbase + q];
    __syncthreads();

    ull acc2[4][4];
#pragma unroll
    for (int i = 0; i < 4; i++)
#pragma unroll
        for (int j = 0; j < 4; j++) acc2[i][j] = 0ull;

#pragma unroll
    for (int p = 0; p < 4; p++) {
        int i = tid + p * 512;
        int kk = i & 15, bb = i >> 4;
        As[kk * 132 + bb] = Theta[(b0 + bb) * 16384 + spmap[kk]];
    }
#pragma unroll
    for (int p = 0; p < 4; p++) {
        int i = tid + p * 512;
        Bs[i] = g_W1s[(kbase + (i >> 7)) * 128 + (i & 127)];
    }
    __syncthreads();

    float pa[4], pb[4];
    for (int c = 0; c < 17; c++) {
        if (c < 16) {
            int kc = (c + 1) * 16;
#pragma unroll
            for (int p = 0; p < 4; p++) {
                int i = tid + p * 512;
                int kk = i & 15, bb = i >> 4;
                pa[p] = Theta[(b0 + bb) * 16384 + spmap[kc + kk]];
            }
#pragma unroll
            for (int p = 0; p < 4; p++) {
                int i = tid + p * 512;
                pb[p] = g_W1s[(kbase + kc + (i >> 7)) * 128 + (i & 127)];
            }
        }
        const float* Ab = As + (c & 1) * (16 * 132);
        const float* Bb = Bs + (c & 1) * (16 * 128);
#pragma unroll 8
        for (int s = 0; s < 16; s++)
            mma_step512(acc2, Ab + s * 132 + ty * 8, Bb + s * 128 + tx * 4);
        if (c < 16) {
            float* An = As + ((c + 1) & 1) * (16 * 132);
            float* Bn = Bs + ((c + 1) & 1) * (16 * 128);
#pragma unroll
            for (int p = 0; p < 4; p++) {
                int i = tid + p * 512;
                An[(i & 15) * 132 + (i >> 4)] = pa[p];
            }
#pragma unroll
            for (int p = 0; p < 4; p++) {
                int i = tid + p * 512;
                Bn[i] = pb[p];
            }
            __syncthreads();
        }
    }
    float* outp = g_z0p + (blockIdx.y * 1024 + b0) * 128;
#pragma unroll
    for (int i2 = 0; i2 < 4; i2++) {
        float lo[4], hi[4];
#pragma unroll
        for (int j = 0; j < 4; j++) unpack2(acc2[i2][j], lo[j], hi[j]);
        float* p0 = outp + (ty * 8 + 2 * i2) * 128 + tx * 4;
        *(float4*)p0         = make_float4(lo[0], lo[1], lo[2], lo[3]);
        *(float4*)(p0 + 128) = make_float4(hi[0], hi[1], hi[2], hi[3]);
    }
}

// ---------------------------------------------------------------------------
// reduce split-K partials + bias
// ---------------------------------------------------------------------------
__global__ void k_z0red(const float* __restrict__ b1) {
    int idx = blockIdx.x * 256 + threadIdx.x;
    int k = idx & 127;
    float s = (k < 127) ? b1[k] : 0.f;
#pragma unroll
    for (int sp = 0; sp < 32; sp++) s += g_z0p[sp * 131072 + idx];
    g_z0[idx] = s;
}

// ---------------------------------------------------------------------------
// dz[b,t,k] = sum_s D[b,t,s]*U[t,s,k]; D on the fly (diag special case!)
// Quartered over batch: grid (127, 2), b_base selects the quarter.
// ---------------------------------------------------------------------------
__global__ void __launch_bounds__(512, 2) k_dz(const float* __restrict__ Theta,
                                               int b_base) {
    extern __shared__ float sm[];
    float* Us = sm;            // 128*128 (row 127 zeroed)
    float* Ds = sm + 16384;    // 2 * 32*132
    const int tid = threadIdx.x, tx = tid & 31, ty = tid >> 5;
    const int t = blockIdx.x, b0 = b_base + blockIdx.y * 128;

    {
        const float4* Usrc = (const float4*)(g_Upad + t * 16256);
        float4* Ud = (float4*)Us;
        for (int i = tid; i < 4064; i += 512) Ud[i] = Usrc[i];
        for (int i = 16256 + tid; i < 16384; i += 512) Us[i] = 0.f;
    }

    auto loadD = [&](int c, int p) -> float {
        int i = tid + p * 512;
        int s = i & 31, bb = i >> 5;
        int sg = c * 32 + s;
        if (sg >= 127) return 0.f;
        const float* Tb = Theta + (size_t)(b0 + bb) * 16384;
        if (sg == t)
            return Tb[(t << 7) + t] - Tb[((t + 1) << 7) + (t + 1)];
        int g = sg + (sg >= t);
        return Tb[(t << 7) + g] - Tb[((t + 1) << 7) + g];
    };

#pragma unroll
    for (int p = 0; p < 8; p++) {
        int i = tid + p * 512;
        Ds[(i & 31) * 132 + (i >> 5)] = loadD(0, p);
    }
    __syncthreads();

    ull acc2[4][4];
#pragma unroll
    for (int i = 0; i < 4; i++)
#pragma unroll
        for (int j = 0; j < 4; j++) acc2[i][j] = 0ull;

    float pre[8];
    for (int c = 0; c < 4; c++) {
        if (c < 3) {
#pragma unroll
            for (int p = 0; p < 8; p++) pre[p] = loadD(c + 1, p);
        }
        const float* Db = Ds + (c & 1) * 4224;
        const float* Ub = Us + c * 32 * 128;
#pragma unroll 8
        for (int s = 0; s < 32; s++)
            mma_step512(acc2, Db + s * 132 + ty * 8, Ub + s * 128 + tx * 4);
        if (c < 3) {
            float* Dn = Ds + ((c + 1) & 1) * 4224;
#pragma unroll
            for (int p = 0; p < 8; p++) {
                int i = tid + p * 512;
                Dn[(i & 31) * 132 + (i >> 5)] = pre[p];
            }
            __syncthreads();
        }
    }
#pragma unroll
    for (int i2 = 0; i2 < 4; i2++) {
        float lo[4], hi[4];
#pragma unroll
        for (int j = 0; j < 4; j++) unpack2(acc2[i2][j], lo[j], hi[j]);
        int bb0 = b0 + ty * 8 + 2 * i2;
        float* p0 = g_dz + ((size_t)bb0 * 127 + t) * 128 + tx * 4;
        float* p1 = g_dz + ((size_t)(bb0 + 1) * 127 + t) * 128 + tx * 4;
        *(float4*)p0 = make_float4(lo[0], lo[1], lo[2], lo[3]);
        *(float4*)p1 = make_float4(hi[0], hi[1], hi[2], hi[3]);
    }
}

// ---------------------------------------------------------------------------
// Fused: SEGMENTED prefix+ReLU into smem h_T[k][t], GEMM h@W2 streamed,
// bias, out assembly (Theta symmetry). Quartered: grid 256, b_base offset.
// ---------------------------------------------------------------------------
__global__ void __launch_bounds__(512, 2) k_g2out(const float* __restrict__ Theta,
                                                  const float* __restrict__ W2,
                                                  const float* __restrict__ b2,
                                                  float* __restrict__ out,
                                                  int b_base) {
    extern __shared__ float sm[];
    float* Ht  = sm;                       // [k][t] pad 132; later t12n stage
    float* Ws  = sm + 128 * 132;           // 2 * 32*128 W2 chunks
    float* car = sm + 128 * 132 + 8192;    // [seg][k] 4*128
    const int tid = threadIdx.x, tx = tid & 31, ty = tid >> 5;
    const int b = b_base + blockIdx.x;

    // Phase 0a: all threads load W2 chunk 0 into buffer 0.
#pragma unroll
    for (int p = 0; p < 8; p++) {
        int i = tid + p * 512;
        int kk = i >> 7, ss = i & 127;
        Ws[i] = (ss < 127) ? W2[kk * 127 + ss] : 0.f;
    }

    // Phase 0b: segmented prefix partials. (k, seg) = (tid&127, tid>>7).
    {
        const int k = tid & 127, seg = tid >> 7, T0 = seg * 32;
        const float* dzp = g_dz + (size_t)b * 127 * 128 + k;
        float acc = 0.f;
#pragma unroll 4
        for (int tt = 0; tt < 32; tt++) {
            Ht[k * 132 + T0 + tt] = acc;
            int c = T0 + tt;
            if (c < 127) acc += dzp[c * 128];
        }
        car[seg * 128 + k] = acc;
    }
    __syncthreads();

    // Phase 0c: carries (exclusive scan over 4 segments, per k).
    if (tid < 128) {
        float c0 = g_z0[b * 128 + tid];
        float c1 = c0 + car[0 * 128 + tid];
        float c2 = c1 + car[1 * 128 + tid];
        float c3 = c2 + car[2 * 128 + tid];
        car[0 * 128 + tid] = c0;
        car[1 * 128 + tid] = c1;
        car[2 * 128 + tid] = c2;
        car[3 * 128 + tid] = c3;
    }
    __syncthreads();

    // Phase 0d: add carry + ReLU in place.
    {
        const int k = tid & 127, seg = tid >> 7, T0 = seg * 32;
        float C = car[seg * 128 + k];
#pragma unroll 4
        for (int tt = 0; tt < 32; tt++) {
            float v = C + Ht[k * 132 + T0 + tt];
            Ht[k * 132 + T0 + tt] = fmaxf(v, 0.f);
        }
    }
    __syncthreads();

    ull acc2[4][4];
#pragma unroll
    for (int i = 0; i < 4; i++)
#pragma unroll
        for (int j = 0; j < 4; j++) acc2[i][j] = 0ull;

    float pre[8];
    for (int c = 0; c < 4; c++) {
        if (c < 3) {
#pragma unroll
            for (int p = 0; p < 8; p++) {
                int i = tid + p * 512;
                int kk = (c + 1) * 32 + (i >> 7), ss = i & 127;
                pre[p] = (kk < 127 && ss < 127) ? W2[kk * 127 + ss] : 0.f;
            }
        }
        const float* Wb = Ws + (c & 1) * 4096;
#pragma unroll 8
        for (int s = 0; s < 32; s++)
            mma_step512(acc2, Ht + (c * 32 + s) * 132 + ty * 8, Wb + s * 128 + tx * 4);
        if (c < 3) {
            float* Wn = Ws + ((c + 1) & 1) * 4096;
#pragma unroll
            for (int p = 0; p < 8; p++) {
                int i = tid + p * 512;
                Wn[i] = pre[p];
            }
            __syncthreads();
        }
    }
    __syncthreads();   // all Ht reads done before reuse as stage

    float b2v[4];
#pragma unroll
    for (int j = 0; j < 4; j++) {
        int ss = tx * 4 + j;
        b2v[j] = (ss < 127) ? b2[ss] : 0.f;
    }

    // stage t12n tile into Ht: [r][132] (rows = t, cols = s)
#pragma unroll
    for (int i2 = 0; i2 < 4; i2++) {
        float lo[4], hi[4];
#pragma unroll
        for (int j = 0; j < 4; j++) unpack2(acc2[i2][j], lo[j], hi[j]);
        int r0 = ty * 8 + 2 * i2;
#pragma unroll
        for (int j = 0; j < 4; j++) {
            Ht[r0 * 132 + tx * 4 + j]       = lo[j] + b2v[j];
            Ht[(r0 + 1) * 132 + tx * 4 + j] = hi[j] + b2v[j];
        }
    }
    __syncthreads();

    // out[b,r,c]: diag = th; off-diag = th + 129*(t12n[max][min] - th)
    const float* Tb = Theta + (size_t)b * 16384;
    float* Ob = out + (size_t)b * 16384;
    for (int idx4 = tid; idx4 < 4096; idx4 += 512) {
        int r = idx4 >> 5;
        int c0 = (idx4 & 31) * 4;
        float4 th4 = *(const float4*)(Tb + r * 128 + c0);
        float th[4] = {th4.x, th4.y, th4.z, th4.w};
        float o[4];
#pragma unroll
        for (int l = 0; l < 4; l++) {
            int c = c0 + l;
            if (r == c) {
                o[l] = th[l];
            } else {
                int T = r > c ? r : c;
                int m = r < c ? r : c;
                float tn = Ht[T * 132 + m];
                o[l] = th[l] + 129.f * (tn - th[l]);
            }
        }
        *(float4*)(Ob + r * 128 + c0) = make_float4(o[0], o[1], o[2], o[3]);
    }
}

// ---------------------------------------------------------------------------
// Launch: software pipeline over batch quarters.
//   s0   : build -> dz(q0) -> dz(q1) -> dz(q2) -> dz(q3)
//   s_aux: z0s -> z0red -> g2out(q0) -> g2out(q1) -> g2out(q2) -> g2out(q3)
// with per-quarter events dz(q) -> g2out(q); final join back to s0.
// ---------------------------------------------------------------------------
extern "C" void kernel_launch(void* const* d_in, const int* in_sizes, int n_in,
                              void* d_out, int out_size) {
    const float* Theta = (const float*)d_in[0];
    const float* W1    = (const float*)d_in[1];
    const float* b1    = (const float*)d_in[2];
    const float* W2    = (const float*)d_in[3];
    const float* b2    = (const float*)d_in[4];
    float* out = (float*)d_out;
    (void)in_sizes; (void)n_in; (void)out_size;

    static cudaStream_t s_aux = nullptr;
    static cudaEvent_t ev_root = nullptr, ev_q[4] = {}, ev_done = nullptr;
    if (s_aux == nullptr) {                 // first call is outside capture
        cudaStreamCreateWithFlags(&s_aux, cudaStreamNonBlocking);
        cudaEventCreateWithFlags(&ev_root, cudaEventDisableTiming);
        for (int q = 0; q < 4; q++)
            cudaEventCreateWithFlags(&ev_q[q], cudaEventDisableTiming);
        cudaEventCreateWithFlags(&ev_done, cudaEventDisableTiming);
    }

    const int SM_Z0 = (2 * 16 * 132 + 2 * 16 * 128) * 4 + KPER * 4;
    const int SM_DZ = (16384 + 2 * 32 * 132) * 4;                    // 99328
    const int SM_G2 = (128 * 132 + 2 * 32 * 128 + 512) * 4;          // 102400
    cudaFuncSetAttribute(k_z0s,   cudaFuncAttributeMaxDynamicSharedMemorySize, SM_Z0);
    cudaFuncSetAttribute(k_dz,    cudaFuncAttributeMaxDynamicSharedMemorySize, SM_DZ);
    cudaFuncSetAttribute(k_g2out, cudaFuncAttributeMaxDynamicSharedMemorySize, SM_G2);

    k_build<<<640, 128>>>(W1);

    // fork: aux stream runs the z0 chain, then the g2out quarters
    cudaEventRecord(ev_root, 0);
    cudaStreamWaitEvent(s_aux, ev_root, 0);
    k_z0s<<<dim3(8, 32), 512, SM_Z0, s_aux>>>(Theta);
    k_z0red<<<512, 256, 0, s_aux>>>(b1);

    for (int q = 0; q < 4; q++) {
        k_dz<<<dim3(127, 2), 512, SM_DZ>>>(Theta, q * 256);
        cudaEventRecord(ev_q[q], 0);
        cudaStreamWaitEvent(s_aux, ev_q[q], 0);
        k_g2out<<<256, 512, SM_G2, s_aux>>>(Theta, W2, b2, out, q * 256);
    }

    // join back to the origin stream
    cudaEventRecord(ev_done, s_aux);
    cudaStreamWaitEvent(0, ev_done, 0);
}